// round 7
// baseline (speedup 1.0000x reference)
#include <cuda_runtime.h>
#include <cstdint>

#define N_NODES 100000
#define F_IN    128
#define F_HID   64
#define F_OUT   16
#define E_MAX   1600000
#define CAP     128          // padded in-neighbor bucket capacity (Poisson(16) tail ~0)

// Scratch (allocation-free rule: __device__ globals).
// NOTE: never pass these as kernel args from host — host sees the shadow
// symbol and ATS on GB300 makes the bogus access succeed silently.
__device__ float g_dis[N_NODES];              // rsqrt(1 + in-degree)
__device__ int   g_cnt[N_NODES];              // in-degree counters (zeroed per launch)
__device__ int   g_bucket[(size_t)N_NODES * CAP];  // in-neighbor src lists
__device__ float g_xw1[N_NODES * F_HID];      // x @ W1
__device__ float g_h  [N_NODES * F_HID];      // layer-1 output (aggregated)
__device__ float g_hw2[N_NODES * F_OUT];      // relu(h) @ W2
__device__ int   g_is64;

// ---------------------------------------------------------------------------
// edge dtype sniff: int64 little-endian with values < 2^31 has zero odd words
// ---------------------------------------------------------------------------
__global__ void k_sniff(const int* __restrict__ ei32) {
    int all_zero = 1;
#pragma unroll
    for (int i = 0; i < 16; ++i)
        if (ei32[2 * i + 1] != 0) all_zero = 0;
    g_is64 = all_zero;
}

// ---------------------------------------------------------------------------
// bucket build: decode edge, cnt[dst]++ (also serves as degree), store src
// ---------------------------------------------------------------------------
__global__ void k_build(const void* __restrict__ ei, int E) {
    int e = blockIdx.x * blockDim.x + threadIdx.x;
    if (e >= E) return;
    int s, d;
    if (g_is64) {
        s = (int)((const long long*)ei)[e];
        d = (int)((const long long*)ei)[e + E];
    } else {
        s = ((const int*)ei)[e];
        d = ((const int*)ei)[e + E];
    }
    if (s < 0) s = 0; if (s >= N_NODES) s = N_NODES - 1;
    if (d < 0) d = 0; if (d >= N_NODES) d = N_NODES - 1;
    int pos = atomicAdd(&g_cnt[d], 1);
    if (pos < CAP) g_bucket[(size_t)d * CAP + pos] = s;
}

__global__ void k_rsqrt_deg(int n) {
    int i = blockIdx.x * blockDim.x + threadIdx.x;
    if (i < n) g_dis[i] = rsqrtf(1.0f + (float)g_cnt[i]);   // +1 = self-loop
}

// ---------------------------------------------------------------------------
// GEMM1: g_xw1[M,64] = X[M,128] @ W[128,64]
// 64x64 block tile, 4x4 register micro-tile, K split in two 64-chunks.
// ---------------------------------------------------------------------------
__global__ void k_gemm1(const float* __restrict__ X, const float* __restrict__ W,
                        int M) {
    __shared__ float sXT[64][68];   // transposed X tile: [k][m]
    __shared__ float sW [64][64];   // [k][n]

    const int t  = threadIdx.x;          // 256 threads
    const int tx = t & 15, ty = t >> 4;
    const int row0 = blockIdx.x * 64;
    const int lr = t >> 2;               // 0..63
    const int lc = t & 3;                // 0..3

    float acc[4][4];
#pragma unroll
    for (int i = 0; i < 4; i++)
#pragma unroll
        for (int j = 0; j < 4; j++) acc[i][j] = 0.f;

    for (int kt = 0; kt < 2; ++kt) {
#pragma unroll
        for (int i = 0; i < 4; ++i) {
            int c0 = (lc + 4 * i) * 4;           // 0..60, step 4, 16B aligned cols
            int gr = row0 + lr;
            float4 v = make_float4(0.f, 0.f, 0.f, 0.f);
            if (gr < M)
                v = *(const float4*)(X + (size_t)gr * F_IN + kt * 64 + c0);
            sXT[c0 + 0][lr] = v.x;
            sXT[c0 + 1][lr] = v.y;
            sXT[c0 + 2][lr] = v.z;
            sXT[c0 + 3][lr] = v.w;
            float4 wv = *(const float4*)(W + (size_t)(kt * 64 + lr) * F_HID + c0);
            *(float4*)&sW[lr][c0] = wv;
        }
        __syncthreads();

#pragma unroll 8
        for (int kk = 0; kk < 64; ++kk) {
            float4 xv = *(const float4*)&sXT[kk][ty * 4];
            float4 wv = *(const float4*)&sW[kk][tx * 4];
            float xa[4] = {xv.x, xv.y, xv.z, xv.w};
            float wa[4] = {wv.x, wv.y, wv.z, wv.w};
#pragma unroll
            for (int i = 0; i < 4; i++)
#pragma unroll
                for (int j = 0; j < 4; j++)
                    acc[i][j] += xa[i] * wa[j];
        }
        __syncthreads();
    }

#pragma unroll
    for (int i = 0; i < 4; i++) {
        int gr = row0 + ty * 4 + i;
        if (gr < M) {
            float4 o = make_float4(acc[i][0], acc[i][1], acc[i][2], acc[i][3]);
            *(float4*)(g_xw1 + (size_t)gr * F_HID + tx * 4) = o;
        }
    }
}

// ---------------------------------------------------------------------------
// gather layer 1: one warp per dst node, float2 per lane (64 feats)
//   h[d] = dis[d] * sum_s xw1[s]*dis[s]  +  dis[d]^2 * xw1[d]
// 4x unrolled: 4 independent 256B row loads in flight per warp (MLP>=4).
// ---------------------------------------------------------------------------
__global__ void k_gather1(int N) {
    int warp = (blockIdx.x * blockDim.x + threadIdx.x) >> 5;
    int lane = threadIdx.x & 31;
    if (warp >= N) return;
    const int d = warp;
    int deg = g_cnt[d]; if (deg > CAP) deg = CAP;
    const int* bk = g_bucket + (size_t)d * CAP;

    float2 a0 = make_float2(0.f, 0.f), a1 = a0, a2 = a0, a3 = a0;
    int i = 0;
    for (; i + 4 <= deg; i += 4) {
        int s0 = bk[i + 0], s1 = bk[i + 1], s2 = bk[i + 2], s3 = bk[i + 3];
        float d0 = __ldg(&g_dis[s0]), d1 = __ldg(&g_dis[s1]);
        float d2 = __ldg(&g_dis[s2]), d3 = __ldg(&g_dis[s3]);
        float2 v0 = __ldg((const float2*)(g_xw1 + (size_t)s0 * F_HID) + lane);
        float2 v1 = __ldg((const float2*)(g_xw1 + (size_t)s1 * F_HID) + lane);
        float2 v2 = __ldg((const float2*)(g_xw1 + (size_t)s2 * F_HID) + lane);
        float2 v3 = __ldg((const float2*)(g_xw1 + (size_t)s3 * F_HID) + lane);
        a0.x += v0.x * d0; a0.y += v0.y * d0;
        a1.x += v1.x * d1; a1.y += v1.y * d1;
        a2.x += v2.x * d2; a2.y += v2.y * d2;
        a3.x += v3.x * d3; a3.y += v3.y * d3;
    }
    for (; i < deg; ++i) {
        int s = bk[i];
        float ds = __ldg(&g_dis[s]);
        float2 v = __ldg((const float2*)(g_xw1 + (size_t)s * F_HID) + lane);
        a0.x += v.x * ds; a0.y += v.y * ds;
    }
    float2 acc = make_float2(a0.x + a1.x + a2.x + a3.x,
                             a0.y + a1.y + a2.y + a3.y);
    float dd = g_dis[d];
    float n2 = dd * dd;
    float2 self = *(const float2*)(g_xw1 + (size_t)d * F_HID + lane * 2);
    float2 h;
    h.x = dd * acc.x + n2 * self.x;
    h.y = dd * acc.y + n2 * self.y;
    *(float2*)(g_h + (size_t)d * F_HID + lane * 2) = h;
}

// ---------------------------------------------------------------------------
// GEMM2 with fused relu+bias on input:
//   g_hw2[M,16] = relu(g_h + b1) @ W2[64,16]
// ---------------------------------------------------------------------------
__global__ void k_gemm2(const float* __restrict__ W2, const float* __restrict__ b1,
                        int M) {
    __shared__ float sW[F_HID * F_OUT];   // 1024
    __shared__ float sH[16][65];
    int t = threadIdx.x;                  // 256 threads, 16 nodes/block
    for (int i = t; i < F_HID * F_OUT; i += 256) sW[i] = W2[i];
    int node0 = blockIdx.x * 16;
    for (int i = t; i < 1024; i += 256) {
        int r = i >> 6, c = i & 63;
        int gn = node0 + r;
        float hv = (gn < M) ? g_h[(size_t)gn * F_HID + c] : 0.f;
        sH[r][c] = fmaxf(hv + b1[c], 0.f);     // fused relu+bias
    }
    __syncthreads();
    int f = t & 15, nl = t >> 4;
    float acc = 0.f;
#pragma unroll
    for (int k = 0; k < F_HID; ++k) acc += sH[nl][k] * sW[k * F_OUT + f];
    int gn = node0 + nl;
    if (gn < M) g_hw2[(size_t)gn * F_OUT + f] = acc;
}

// ---------------------------------------------------------------------------
// gather layer 2: 16 lanes per dst node (one float each), 4x unrolled
//   out[d] = dis[d] * sum_s hw2[s]*dis[s] + dis[d]^2 * hw2[d] + b2
// ---------------------------------------------------------------------------
__global__ void k_gather2(const float* __restrict__ b2, float* __restrict__ out,
                          int N) {
    int tid = blockIdx.x * blockDim.x + threadIdx.x;
    int node = tid >> 4;
    if (node >= N) return;
    int q = tid & 15;
    int deg = g_cnt[node]; if (deg > CAP) deg = CAP;
    const int* bk = g_bucket + (size_t)node * CAP;

    float a0 = 0.f, a1 = 0.f, a2 = 0.f, a3 = 0.f;
    int i = 0;
    for (; i + 4 <= deg; i += 4) {
        int s0 = bk[i + 0], s1 = bk[i + 1], s2 = bk[i + 2], s3 = bk[i + 3];
        a0 += __ldg(&g_hw2[(size_t)s0 * F_OUT + q]) * __ldg(&g_dis[s0]);
        a1 += __ldg(&g_hw2[(size_t)s1 * F_OUT + q]) * __ldg(&g_dis[s1]);
        a2 += __ldg(&g_hw2[(size_t)s2 * F_OUT + q]) * __ldg(&g_dis[s2]);
        a3 += __ldg(&g_hw2[(size_t)s3 * F_OUT + q]) * __ldg(&g_dis[s3]);
    }
    for (; i < deg; ++i) {
        int s = bk[i];
        a0 += __ldg(&g_hw2[(size_t)s * F_OUT + q]) * __ldg(&g_dis[s]);
    }
    float acc = (a0 + a1) + (a2 + a3);
    float dd = g_dis[node];
    out[(size_t)node * F_OUT + q] =
        dd * acc + dd * dd * g_hw2[(size_t)node * F_OUT + q] + b2[q];
}

// ---------------------------------------------------------------------------
extern "C" void kernel_launch(void* const* d_in, const int* in_sizes, int n_in,
                              void* d_out, int out_size) {
    // Bind inputs by element count (robust to metadata ordering); positional fallback.
    const float* x  = (const float*)d_in[0];
    const void*  ei = d_in[1];
    const float* W1 = (const float*)d_in[2];
    const float* b1 = (const float*)d_in[3];
    const float* W2 = (const float*)d_in[4];
    const float* b2 = (const float*)d_in[5];
    int x_elems = in_sizes[0];
    int e_elems = in_sizes[1];
    for (int i = 0; i < n_in; ++i) {
        int sz = in_sizes[i];
        if (sz == N_NODES * F_IN)      { x  = (const float*)d_in[i]; x_elems = sz; }
        else if (sz == 2 * E_MAX)      { ei = d_in[i];               e_elems = sz; }
        else if (sz == F_IN * F_HID)   { W1 = (const float*)d_in[i]; }
        else if (sz == F_HID)          { b1 = (const float*)d_in[i]; }
        else if (sz == F_HID * F_OUT)  { W2 = (const float*)d_in[i]; }
        else if (sz == F_OUT)          { b2 = (const float*)d_in[i]; }
    }
    float* out = (float*)d_out;

    const int N = x_elems / F_IN;       // 100000
    const int E = e_elems / 2;          // 1600000

    const int T = 256;

    // Lazily-created side stream + fork/join events (created on the first,
    // uncaptured, correctness call; reused during capture). Creation does not
    // change the per-call device work.
    static cudaStream_t s_side = 0;
    static cudaEvent_t  s_fork = 0, s_join = 0;
    if (!s_side) {
        if (cudaStreamCreateWithFlags(&s_side, cudaStreamNonBlocking) != cudaSuccess)
            s_side = 0;
        if (s_side) {
            cudaEventCreateWithFlags(&s_fork, cudaEventDisableTiming);
            cudaEventCreateWithFlags(&s_join, cudaEventDisableTiming);
        }
    }

    void* cntPtr = nullptr;
    cudaGetSymbolAddress(&cntPtr, g_cnt);

    const bool fork = (s_side != 0);

    // fork: GEMM1 (only needs x,W1) runs concurrently with the graph build chain
    if (fork) {
        cudaEventRecord(s_fork, 0);
        cudaStreamWaitEvent(s_side, s_fork, 0);
        k_gemm1<<<(N + 63) / 64, 256, 0, s_side>>>(x, W1, N);
        cudaEventRecord(s_join, s_side);
    }

    // graph build chain on the main stream (replay-safe: cnt re-zeroed per launch)
    k_sniff<<<1, 1>>>((const int*)ei);
    cudaMemsetAsync(cntPtr, 0, (size_t)N * sizeof(int), 0);
    k_build<<<(E + T - 1) / T, T>>>(ei, E);
    k_rsqrt_deg<<<(N + T - 1) / T, T>>>(N);

    if (fork) {
        cudaStreamWaitEvent(0, s_join, 0);
    } else {
        k_gemm1<<<(N + 63) / 64, 256>>>(x, W1, N);
    }

    // layer 1 aggregation
    k_gather1<<<(N * 32 + T - 1) / T, T>>>(N);

    // layer 2
    k_gemm2<<<(N + 15) / 16, 256>>>(W2, b1, N);
    k_gather2<<<(N * 16 + T - 1) / T, T>>>(b2, out, N);
}

// round 8
// speedup vs baseline: 1.0105x; 1.0105x over previous
#include <cuda_runtime.h>
#include <cstdint>

#define N_NODES 100000
#define F_IN    128
#define F_HID   64
#define F_OUT   16
#define E_MAX   1600000
#define CAP     128          // padded in-neighbor bucket capacity (Poisson(16) tail ~0)

// Scratch (allocation-free rule: __device__ globals).
// NOTE: never pass these as kernel args from host — host sees the shadow
// symbol and ATS on GB300 makes the bogus access succeed silently.
__device__ float g_dis [N_NODES];             // rsqrt(1 + in-degree)
__device__ int   g_cnt [N_NODES];             // in-degree counters (zeroed per launch)
__device__ int   g_bucket[(size_t)N_NODES * CAP];  // in-neighbor src lists
__device__ float g_xws [N_NODES * F_HID];     // (x @ W1) * dis   (pre-scaled)
__device__ float g_h   [N_NODES * F_HID];     // layer-1 aggregated output
__device__ float g_hw2s[N_NODES * F_OUT];     // (relu(h+b1) @ W2) * dis (pre-scaled)
__device__ int   g_is64;

// ---------------------------------------------------------------------------
// edge dtype sniff: int64 little-endian with values < 2^31 has zero odd words
// ---------------------------------------------------------------------------
__global__ void k_sniff(const int* __restrict__ ei32) {
    int all_zero = 1;
#pragma unroll
    for (int i = 0; i < 16; ++i)
        if (ei32[2 * i + 1] != 0) all_zero = 0;
    g_is64 = all_zero;
}

// ---------------------------------------------------------------------------
// bucket build: decode edge, cnt[dst]++ (also serves as degree), store src
// ---------------------------------------------------------------------------
__global__ void k_build(const void* __restrict__ ei, int E) {
    int e = blockIdx.x * blockDim.x + threadIdx.x;
    if (e >= E) return;
    int s, d;
    if (g_is64) {
        s = (int)((const long long*)ei)[e];
        d = (int)((const long long*)ei)[e + E];
    } else {
        s = ((const int*)ei)[e];
        d = ((const int*)ei)[e + E];
    }
    if (s < 0) s = 0; if (s >= N_NODES) s = N_NODES - 1;
    if (d < 0) d = 0; if (d >= N_NODES) d = N_NODES - 1;
    int pos = atomicAdd(&g_cnt[d], 1);
    if (pos < CAP) g_bucket[(size_t)d * CAP + pos] = s;
}

__global__ void k_rsqrt_deg(int n) {
    int i = blockIdx.x * blockDim.x + threadIdx.x;
    if (i < n) g_dis[i] = rsqrtf(1.0f + (float)g_cnt[i]);   // +1 = self-loop
}

// ---------------------------------------------------------------------------
// GEMM1 + fused dis pre-scale:  g_xws[M,64] = (X[M,128] @ W[128,64]) * dis
// 64x64 block tile, 4x4 register micro-tile, K split in two 64-chunks.
// ---------------------------------------------------------------------------
__global__ void k_gemm1(const float* __restrict__ X, const float* __restrict__ W,
                        int M) {
    __shared__ float sXT[64][68];   // transposed X tile: [k][m]
    __shared__ float sW [64][64];   // [k][n]

    const int t  = threadIdx.x;          // 256 threads
    const int tx = t & 15, ty = t >> 4;
    const int row0 = blockIdx.x * 64;
    const int lr = t >> 2;               // 0..63
    const int lc = t & 3;                // 0..3

    float acc[4][4];
#pragma unroll
    for (int i = 0; i < 4; i++)
#pragma unroll
        for (int j = 0; j < 4; j++) acc[i][j] = 0.f;

    for (int kt = 0; kt < 2; ++kt) {
#pragma unroll
        for (int i = 0; i < 4; ++i) {
            int c0 = (lc + 4 * i) * 4;           // 0..60, step 4, 16B aligned cols
            int gr = row0 + lr;
            float4 v = make_float4(0.f, 0.f, 0.f, 0.f);
            if (gr < M)
                v = *(const float4*)(X + (size_t)gr * F_IN + kt * 64 + c0);
            sXT[c0 + 0][lr] = v.x;
            sXT[c0 + 1][lr] = v.y;
            sXT[c0 + 2][lr] = v.z;
            sXT[c0 + 3][lr] = v.w;
            float4 wv = *(const float4*)(W + (size_t)(kt * 64 + lr) * F_HID + c0);
            *(float4*)&sW[lr][c0] = wv;
        }
        __syncthreads();

#pragma unroll 8
        for (int kk = 0; kk < 64; ++kk) {
            float4 xv = *(const float4*)&sXT[kk][ty * 4];
            float4 wv = *(const float4*)&sW[kk][tx * 4];
            float xa[4] = {xv.x, xv.y, xv.z, xv.w};
            float wa[4] = {wv.x, wv.y, wv.z, wv.w};
#pragma unroll
            for (int i = 0; i < 4; i++)
#pragma unroll
                for (int j = 0; j < 4; j++)
                    acc[i][j] += xa[i] * wa[j];
        }
        __syncthreads();
    }

#pragma unroll
    for (int i = 0; i < 4; i++) {
        int gr = row0 + ty * 4 + i;
        if (gr < M) {
            float ds = g_dis[gr];
            float4 o = make_float4(acc[i][0] * ds, acc[i][1] * ds,
                                   acc[i][2] * ds, acc[i][3] * ds);
            *(float4*)(g_xws + (size_t)gr * F_HID + tx * 4) = o;
        }
    }
}

// ---------------------------------------------------------------------------
// gather layer 1: one warp per dst node, float2 per lane (64 feats)
//   h[d] = dis[d] * ( xws[d] + sum_s xws[s] )
// 4x unrolled: 4 independent 256B row loads in flight per warp (MLP>=4).
// ---------------------------------------------------------------------------
__global__ void k_gather1(int N) {
    int warp = (blockIdx.x * blockDim.x + threadIdx.x) >> 5;
    int lane = threadIdx.x & 31;
    if (warp >= N) return;
    const int d = warp;
    int deg = g_cnt[d]; if (deg > CAP) deg = CAP;
    const int* bk = g_bucket + (size_t)d * CAP;

    // self term folded as a0 seed
    float2 a0 = __ldg((const float2*)(g_xws + (size_t)d * F_HID) + lane);
    float2 a1 = make_float2(0.f, 0.f), a2 = a1, a3 = a1;
    int i = 0;
    for (; i + 4 <= deg; i += 4) {
        int s0 = bk[i + 0], s1 = bk[i + 1], s2 = bk[i + 2], s3 = bk[i + 3];
        float2 v0 = __ldg((const float2*)(g_xws + (size_t)s0 * F_HID) + lane);
        float2 v1 = __ldg((const float2*)(g_xws + (size_t)s1 * F_HID) + lane);
        float2 v2 = __ldg((const float2*)(g_xws + (size_t)s2 * F_HID) + lane);
        float2 v3 = __ldg((const float2*)(g_xws + (size_t)s3 * F_HID) + lane);
        a0.x += v0.x; a0.y += v0.y;
        a1.x += v1.x; a1.y += v1.y;
        a2.x += v2.x; a2.y += v2.y;
        a3.x += v3.x; a3.y += v3.y;
    }
    for (; i < deg; ++i) {
        int s = bk[i];
        float2 v = __ldg((const float2*)(g_xws + (size_t)s * F_HID) + lane);
        a0.x += v.x; a0.y += v.y;
    }
    float dd = g_dis[d];
    float2 h;
    h.x = dd * ((a0.x + a1.x) + (a2.x + a3.x));
    h.y = dd * ((a0.y + a1.y) + (a2.y + a3.y));
    *(float2*)(g_h + (size_t)d * F_HID + lane * 2) = h;
}

// ---------------------------------------------------------------------------
// GEMM2 with fused relu+bias on input and dis pre-scale on output:
//   g_hw2s[M,16] = ( relu(g_h + b1) @ W2[64,16] ) * dis
// ---------------------------------------------------------------------------
__global__ void k_gemm2(const float* __restrict__ W2, const float* __restrict__ b1,
                        int M) {
    __shared__ float sW[F_HID * F_OUT];   // 1024
    __shared__ float sH[16][65];
    int t = threadIdx.x;                  // 256 threads, 16 nodes/block
    for (int i = t; i < F_HID * F_OUT; i += 256) sW[i] = W2[i];
    int node0 = blockIdx.x * 16;
    for (int i = t; i < 1024; i += 256) {
        int r = i >> 6, c = i & 63;
        int gn = node0 + r;
        float hv = (gn < M) ? g_h[(size_t)gn * F_HID + c] : 0.f;
        sH[r][c] = fmaxf(hv + b1[c], 0.f);     // fused relu+bias
    }
    __syncthreads();
    int f = t & 15, nl = t >> 4;
    float acc = 0.f;
#pragma unroll
    for (int k = 0; k < F_HID; ++k) acc += sH[nl][k] * sW[k * F_OUT + f];
    int gn = node0 + nl;
    if (gn < M) g_hw2s[(size_t)gn * F_OUT + f] = acc * g_dis[gn];
}

// ---------------------------------------------------------------------------
// gather layer 2: 16 lanes per dst node (one float each), 4x unrolled
//   out[d] = dis[d] * ( hw2s[d] + sum_s hw2s[s] ) + b2
// ---------------------------------------------------------------------------
__global__ void k_gather2(const float* __restrict__ b2, float* __restrict__ out,
                          int N) {
    int tid = blockIdx.x * blockDim.x + threadIdx.x;
    int node = tid >> 4;
    if (node >= N) return;
    int q = tid & 15;
    int deg = g_cnt[node]; if (deg > CAP) deg = CAP;
    const int* bk = g_bucket + (size_t)node * CAP;

    float a0 = __ldg(&g_hw2s[(size_t)node * F_OUT + q]);   // self term
    float a1 = 0.f, a2 = 0.f, a3 = 0.f;
    int i = 0;
    for (; i + 4 <= deg; i += 4) {
        int s0 = bk[i + 0], s1 = bk[i + 1], s2 = bk[i + 2], s3 = bk[i + 3];
        a0 += __ldg(&g_hw2s[(size_t)s0 * F_OUT + q]);
        a1 += __ldg(&g_hw2s[(size_t)s1 * F_OUT + q]);
        a2 += __ldg(&g_hw2s[(size_t)s2 * F_OUT + q]);
        a3 += __ldg(&g_hw2s[(size_t)s3 * F_OUT + q]);
    }
    for (; i < deg; ++i) {
        int s = bk[i];
        a0 += __ldg(&g_hw2s[(size_t)s * F_OUT + q]);
    }
    float acc = (a0 + a1) + (a2 + a3);
    out[(size_t)node * F_OUT + q] = g_dis[node] * acc + b2[q];
}

// ---------------------------------------------------------------------------
extern "C" void kernel_launch(void* const* d_in, const int* in_sizes, int n_in,
                              void* d_out, int out_size) {
    // Bind inputs by element count (robust to metadata ordering); positional fallback.
    const float* x  = (const float*)d_in[0];
    const void*  ei = d_in[1];
    const float* W1 = (const float*)d_in[2];
    const float* b1 = (const float*)d_in[3];
    const float* W2 = (const float*)d_in[4];
    const float* b2 = (const float*)d_in[5];
    int x_elems = in_sizes[0];
    int e_elems = in_sizes[1];
    for (int i = 0; i < n_in; ++i) {
        int sz = in_sizes[i];
        if (sz == N_NODES * F_IN)      { x  = (const float*)d_in[i]; x_elems = sz; }
        else if (sz == 2 * E_MAX)      { ei = d_in[i];               e_elems = sz; }
        else if (sz == F_IN * F_HID)   { W1 = (const float*)d_in[i]; }
        else if (sz == F_HID)          { b1 = (const float*)d_in[i]; }
        else if (sz == F_HID * F_OUT)  { W2 = (const float*)d_in[i]; }
        else if (sz == F_OUT)          { b2 = (const float*)d_in[i]; }
    }
    float* out = (float*)d_out;

    const int N = x_elems / F_IN;       // 100000
    const int E = e_elems / 2;          // 1600000

    const int T = 256;

    void* cntPtr = nullptr;
    cudaGetSymbolAddress(&cntPtr, g_cnt);

    // graph build chain, single stream (fork experiment in R7 regressed)
    k_sniff<<<1, 1>>>((const int*)ei);
    cudaMemsetAsync(cntPtr, 0, (size_t)N * sizeof(int), 0);
    k_build<<<(E + T - 1) / T, T>>>(ei, E);
    k_rsqrt_deg<<<(N + T - 1) / T, T>>>(N);

    // layer 1 (dis available -> pre-scaled GEMM epilogue)
    k_gemm1<<<(N + 63) / 64, 256>>>(x, W1, N);
    k_gather1<<<(N * 32 + T - 1) / T, T>>>(N);

    // layer 2
    k_gemm2<<<(N + 15) / 16, 256>>>(W2, b1, N);
    k_gather2<<<(N * 16 + T - 1) / T, T>>>(b2, out, N);
}

// round 9
// speedup vs baseline: 1.0555x; 1.0445x over previous
#include <cuda_runtime.h>
#include <cstdint>

#define N_NODES 100000
#define F_IN    128
#define F_HID   64
#define F_OUT   16
#define E_MAX   1600000
#define CAP     128          // padded in-neighbor bucket capacity (Poisson(16) tail ~0)

// Scratch (allocation-free rule: __device__ globals).
// NOTE: never pass these as kernel args from host — host sees the shadow
// symbol and ATS on GB300 makes the bogus access succeed silently.
__device__ float g_dis [N_NODES];             // rsqrt(1 + in-degree)
__device__ int   g_cnt [N_NODES];             // in-degree counters (zeroed per launch)
__device__ int   g_bucket[(size_t)N_NODES * CAP];  // in-neighbor src lists
__device__ float g_xws [N_NODES * F_HID];     // (x @ W1) * dis   (pre-scaled)
__device__ float g_h   [N_NODES * F_HID];     // layer-1 aggregated output
__device__ float g_hw2s[N_NODES * F_OUT];     // (relu(h+b1) @ W2) * dis (pre-scaled)
__device__ int   g_is64;

// ---------------------------------------------------------------------------
// edge dtype sniff: int64 little-endian with values < 2^31 has zero odd words
// ---------------------------------------------------------------------------
__global__ void k_sniff(const int* __restrict__ ei32) {
    int all_zero = 1;
#pragma unroll
    for (int i = 0; i < 16; ++i)
        if (ei32[2 * i + 1] != 0) all_zero = 0;
    g_is64 = all_zero;
}

__global__ void k_zero_cnt(int n) {
    int i = blockIdx.x * blockDim.x + threadIdx.x;
    if (i < n) g_cnt[i] = 0;
}

// ---------------------------------------------------------------------------
// bucket build: decode edge, cnt[dst]++ (also serves as degree), store src
// ---------------------------------------------------------------------------
__global__ void k_build(const void* __restrict__ ei, int E) {
    int e = blockIdx.x * blockDim.x + threadIdx.x;
    if (e >= E) return;
    int s, d;
    if (g_is64) {
        s = (int)((const long long*)ei)[e];
        d = (int)((const long long*)ei)[e + E];
    } else {
        s = ((const int*)ei)[e];
        d = ((const int*)ei)[e + E];
    }
    if (s < 0) s = 0; if (s >= N_NODES) s = N_NODES - 1;
    if (d < 0) d = 0; if (d >= N_NODES) d = N_NODES - 1;
    int pos = atomicAdd(&g_cnt[d], 1);
    if (pos < CAP) g_bucket[(size_t)d * CAP + pos] = s;
}

__global__ void k_rsqrt_deg(int n) {
    int i = blockIdx.x * blockDim.x + threadIdx.x;
    if (i < n) g_dis[i] = rsqrtf(1.0f + (float)g_cnt[i]);   // +1 = self-loop
}

// ---------------------------------------------------------------------------
// GEMM1 + fused dis pre-scale:  g_xws[M,64] = (X[M,128] @ W[128,64]) * dis
// 128x64 block tile, 8x4 register micro-tile (32 FFMA : 3 LDS per k-step),
// K split in two 64-chunks. Static smem exactly 48KB.
// ---------------------------------------------------------------------------
__global__ void k_gemm1(const float* __restrict__ X, const float* __restrict__ W,
                        int M) {
    __shared__ float sXT[64][128];  // transposed X tile: [k][m]  (32KB)
    __shared__ float sW [64][64];   // [k][n]                     (16KB)

    const int t  = threadIdx.x;          // 256 threads
    const int tx = t & 15;               // n: 16 groups * 4 cols
    const int ty = t >> 4;               // m: 16 groups * 8 rows
    const int row0 = blockIdx.x * 128;

    float acc[8][4];
#pragma unroll
    for (int i = 0; i < 8; i++)
#pragma unroll
        for (int j = 0; j < 4; j++) acc[i][j] = 0.f;

    for (int kt = 0; kt < 2; ++kt) {
        // load X tile (128 rows x 64 k-cols), transposed into sXT[k][m]
#pragma unroll
        for (int it = 0; it < 8; ++it) {
            int idx = t + it * 256;          // 0..2047
            int row = idx >> 4;              // 0..127
            int c4  = idx & 15;              // float4 col 0..15
            int gr  = row0 + row;
            float4 v = make_float4(0.f, 0.f, 0.f, 0.f);
            if (gr < M)
                v = *(const float4*)(X + (size_t)gr * F_IN + kt * 64 + c4 * 4);
            sXT[c4 * 4 + 0][row] = v.x;
            sXT[c4 * 4 + 1][row] = v.y;
            sXT[c4 * 4 + 2][row] = v.z;
            sXT[c4 * 4 + 3][row] = v.w;
        }
        // load W tile (64 k-rows x 64 n-cols)
#pragma unroll
        for (int it = 0; it < 4; ++it) {
            int idx = t + it * 256;          // 0..1023
            int kr  = idx >> 4;
            int c4  = idx & 15;
            float4 wv = *(const float4*)(W + (size_t)(kt * 64 + kr) * F_HID + c4 * 4);
            *(float4*)&sW[kr][c4 * 4] = wv;
        }
        __syncthreads();

#pragma unroll 4
        for (int kk = 0; kk < 64; ++kk) {
            float4 m0 = *(const float4*)&sXT[kk][ty * 8];
            float4 m1 = *(const float4*)&sXT[kk][ty * 8 + 4];
            float4 nv = *(const float4*)&sW[kk][tx * 4];
            float ma[8] = {m0.x, m0.y, m0.z, m0.w, m1.x, m1.y, m1.z, m1.w};
            float na[4] = {nv.x, nv.y, nv.z, nv.w};
#pragma unroll
            for (int i = 0; i < 8; i++)
#pragma unroll
                for (int j = 0; j < 4; j++)
                    acc[i][j] += ma[i] * na[j];
        }
        __syncthreads();
    }

#pragma unroll
    for (int i = 0; i < 8; i++) {
        int gr = row0 + ty * 8 + i;
        if (gr < M) {
            float ds = g_dis[gr];
            float4 o = make_float4(acc[i][0] * ds, acc[i][1] * ds,
                                   acc[i][2] * ds, acc[i][3] * ds);
            *(float4*)(g_xws + (size_t)gr * F_HID + tx * 4) = o;
        }
    }
}

// ---------------------------------------------------------------------------
// gather layer 1: one warp per dst node, float2 per lane (64 feats)
//   h[d] = dis[d] * ( xws[d] + sum_s xws[s] )
// Simple loop (R6 structure — manual unroll regressed in R7/R8).
// ---------------------------------------------------------------------------
__global__ void k_gather1(int N) {
    int warp = (blockIdx.x * blockDim.x + threadIdx.x) >> 5;
    int lane = threadIdx.x & 31;
    if (warp >= N) return;
    const int d = warp;
    int deg = g_cnt[d]; if (deg > CAP) deg = CAP;
    const int* bk = g_bucket + (size_t)d * CAP;

    // self term as accumulator seed (already pre-scaled by dis[d])
    float2 acc = *((const float2*)(g_xws + (size_t)d * F_HID) + lane);
    for (int i = 0; i < deg; ++i) {
        int s = bk[i];                                   // warp-broadcast
        float2 v = *((const float2*)(g_xws + (size_t)s * F_HID) + lane);
        acc.x += v.x;
        acc.y += v.y;
    }
    float dd = g_dis[d];
    float2 h = make_float2(dd * acc.x, dd * acc.y);
    *(float2*)(g_h + (size_t)d * F_HID + lane * 2) = h;
}

// ---------------------------------------------------------------------------
// GEMM2 with fused relu+bias on input and dis pre-scale on output:
//   g_hw2s[M,16] = ( relu(g_h + b1) @ W2[64,16] ) * dis
// ---------------------------------------------------------------------------
__global__ void k_gemm2(const float* __restrict__ W2, const float* __restrict__ b1,
                        int M) {
    __shared__ float sW[F_HID * F_OUT];   // 1024
    __shared__ float sH[16][65];
    int t = threadIdx.x;                  // 256 threads, 16 nodes/block
    for (int i = t; i < F_HID * F_OUT; i += 256) sW[i] = W2[i];
    int node0 = blockIdx.x * 16;
    for (int i = t; i < 1024; i += 256) {
        int r = i >> 6, c = i & 63;
        int gn = node0 + r;
        float hv = (gn < M) ? g_h[(size_t)gn * F_HID + c] : 0.f;
        sH[r][c] = fmaxf(hv + b1[c], 0.f);     // fused relu+bias
    }
    __syncthreads();
    int f = t & 15, nl = t >> 4;
    float acc = 0.f;
#pragma unroll
    for (int k = 0; k < F_HID; ++k) acc += sH[nl][k] * sW[k * F_OUT + f];
    int gn = node0 + nl;
    if (gn < M) g_hw2s[(size_t)gn * F_OUT + f] = acc * g_dis[gn];
}

// ---------------------------------------------------------------------------
// gather layer 2: 16 lanes per dst node (one float each), simple loop
//   out[d] = dis[d] * ( hw2s[d] + sum_s hw2s[s] ) + b2
// ---------------------------------------------------------------------------
__global__ void k_gather2(const float* __restrict__ b2, float* __restrict__ out,
                          int N) {
    int tid = blockIdx.x * blockDim.x + threadIdx.x;
    int node = tid >> 4;
    if (node >= N) return;
    int q = tid & 15;
    int deg = g_cnt[node]; if (deg > CAP) deg = CAP;
    const int* bk = g_bucket + (size_t)node * CAP;

    float acc = g_hw2s[(size_t)node * F_OUT + q];   // self term (pre-scaled)
    for (int i = 0; i < deg; ++i) {
        int s = bk[i];
        acc += g_hw2s[(size_t)s * F_OUT + q];
    }
    out[(size_t)node * F_OUT + q] = g_dis[node] * acc + b2[q];
}

// ---------------------------------------------------------------------------
extern "C" void kernel_launch(void* const* d_in, const int* in_sizes, int n_in,
                              void* d_out, int out_size) {
    // Bind inputs by element count (robust to metadata ordering); positional fallback.
    const float* x  = (const float*)d_in[0];
    const void*  ei = d_in[1];
    const float* W1 = (const float*)d_in[2];
    const float* b1 = (const float*)d_in[3];
    const float* W2 = (const float*)d_in[4];
    const float* b2 = (const float*)d_in[5];
    int x_elems = in_sizes[0];
    int e_elems = in_sizes[1];
    for (int i = 0; i < n_in; ++i) {
        int sz = in_sizes[i];
        if (sz == N_NODES * F_IN)      { x  = (const float*)d_in[i]; x_elems = sz; }
        else if (sz == 2 * E_MAX)      { ei = d_in[i];               e_elems = sz; }
        else if (sz == F_IN * F_HID)   { W1 = (const float*)d_in[i]; }
        else if (sz == F_HID)          { b1 = (const float*)d_in[i]; }
        else if (sz == F_HID * F_OUT)  { W2 = (const float*)d_in[i]; }
        else if (sz == F_OUT)          { b2 = (const float*)d_in[i]; }
    }
    float* out = (float*)d_out;

    const int N = x_elems / F_IN;       // 100000
    const int E = e_elems / 2;          // 1600000

    const int T = 256;

    // graph build chain, single stream (R6 recipe — fork & memset regressed)
    k_sniff<<<1, 1>>>((const int*)ei);
    k_zero_cnt<<<(N + T - 1) / T, T>>>(N);
    k_build<<<(E + T - 1) / T, T>>>(ei, E);
    k_rsqrt_deg<<<(N + T - 1) / T, T>>>(N);

    // layer 1 (dis available -> pre-scaled GEMM epilogue)
    k_gemm1<<<(N + 127) / 128, 256>>>(x, W1, N);
    k_gather1<<<(N * 32 + T - 1) / T, T>>>(N);

    // layer 2
    k_gemm2<<<(N + 15) / 16, 256>>>(W2, b1, N);
    k_gather2<<<(N * 16 + T - 1) / T, T>>>(b2, out, N);
}

// round 10
// speedup vs baseline: 1.3241x; 1.2544x over previous
#include <cuda_runtime.h>
#include <cstdint>

#define N_NODES 100000
#define F_IN    128
#define F_HID   64
#define F_OUT   16
#define E_MAX   1600000
#define CAP     128          // padded in-neighbor bucket capacity (Poisson(16) tail ~0)

// Scratch (allocation-free rule: __device__ globals).
// NOTE: never pass these as kernel args from host — host sees the shadow
// symbol and ATS on GB300 makes the bogus access succeed silently.
__device__ float g_dis [N_NODES];             // rsqrt(1 + in-degree)
__device__ int   g_cnt [N_NODES];             // in-degree counters (zeroed per launch)
__device__ int   g_bucket[(size_t)N_NODES * CAP];  // in-neighbor src lists
__device__ float g_xws [N_NODES * F_HID];     // (x @ W1) * dis   (pre-scaled)
__device__ float g_h   [N_NODES * F_HID];     // layer-1 aggregated output
__device__ float g_hw2s[N_NODES * F_OUT];     // (relu(h+b1) @ W2) * dis (pre-scaled)
__device__ int   g_is64;

__device__ __forceinline__ float f2tf32(float f) {
    uint32_t r;
    asm("cvt.rna.tf32.f32 %0, %1;" : "=r"(r) : "f"(f));
    return __uint_as_float(r);
}

// ---------------------------------------------------------------------------
// prep: zero counters; thread (0,0) also sniffs edge dtype
// (int64 little-endian with values < 2^31 has zero odd 32-bit words)
// ---------------------------------------------------------------------------
__global__ void k_prep(const int* __restrict__ ei32, int n) {
    int i = blockIdx.x * blockDim.x + threadIdx.x;
    if (i < n) g_cnt[i] = 0;
    if (i == 0) {
        int all_zero = 1;
#pragma unroll
        for (int j = 0; j < 16; ++j)
            if (ei32[2 * j + 1] != 0) all_zero = 0;
        g_is64 = all_zero;
    }
}

// ---------------------------------------------------------------------------
// bucket build: decode edge, cnt[dst]++ (also serves as degree), store src
// ---------------------------------------------------------------------------
__global__ void k_build(const void* __restrict__ ei, int E) {
    int e = blockIdx.x * blockDim.x + threadIdx.x;
    if (e >= E) return;
    int s, d;
    if (g_is64) {
        s = (int)((const long long*)ei)[e];
        d = (int)((const long long*)ei)[e + E];
    } else {
        s = ((const int*)ei)[e];
        d = ((const int*)ei)[e + E];
    }
    if (s < 0) s = 0; if (s >= N_NODES) s = N_NODES - 1;
    if (d < 0) d = 0; if (d >= N_NODES) d = N_NODES - 1;
    int pos = atomicAdd(&g_cnt[d], 1);
    if (pos < CAP) g_bucket[(size_t)d * CAP + pos] = s;
}

__global__ void k_rsqrt_deg(int n) {
    int i = blockIdx.x * blockDim.x + threadIdx.x;
    if (i < n) g_dis[i] = rsqrtf(1.0f + (float)g_cnt[i]);   // +1 = self-loop
}

// ---------------------------------------------------------------------------
// GEMM1 via tf32 mma.sync + fused dis pre-scale:
//   g_xws[M,64] = (X[M,128] @ W[128,64]) * dis
// Block tile 128x64, 8 warps (4 along M x 2 along N), warp tile 32x32,
// mma m16n8k8. K processed in 4 chunks of 32. Operands rounded to tf32
// with cvt.rna at tile-load time (unbiased), fp32 accumulate.
// ---------------------------------------------------------------------------
__global__ void k_gemm1(const float* __restrict__ X, const float* __restrict__ W,
                        int M) {
    __shared__ float sX[128][36];   // [row][k], pad 4 -> fragment LDS conflict-free
    __shared__ float sW[32][72];    // [k][n],  pad 8 -> fragment LDS conflict-free

    const int t    = threadIdx.x;        // 256 threads
    const int lane = t & 31;
    const int warp = t >> 5;             // 0..7
    const int wm   = warp & 3;           // M group (32 rows)
    const int wn   = warp >> 2;          // N group (32 cols)
    const int gid  = lane >> 2;          // 0..7
    const int tig  = lane & 3;           // 0..3
    const int row0 = blockIdx.x * 128;

    float c[2][4][4];
#pragma unroll
    for (int i = 0; i < 2; i++)
#pragma unroll
        for (int j = 0; j < 4; j++)
#pragma unroll
            for (int k = 0; k < 4; k++) c[i][j][k] = 0.f;

    for (int kt = 0; kt < 4; ++kt) {     // K = 128 / 32
        // load X tile: 128 rows x 32 k  (1024 float4, 4 per thread)
#pragma unroll
        for (int it = 0; it < 4; ++it) {
            int idx = t + it * 256;      // 0..1023
            int row = idx >> 3;          // 0..127
            int c4  = idx & 7;           // 0..7
            int gr  = row0 + row;
            float4 v = make_float4(0.f, 0.f, 0.f, 0.f);
            if (gr < M)
                v = *(const float4*)(X + (size_t)gr * F_IN + kt * 32 + c4 * 4);
            float4 tv = make_float4(f2tf32(v.x), f2tf32(v.y), f2tf32(v.z), f2tf32(v.w));
            *(float4*)&sX[row][c4 * 4] = tv;
        }
        // load W tile: 32 k x 64 n (512 float4, 2 per thread)
#pragma unroll
        for (int it = 0; it < 2; ++it) {
            int idx = t + it * 256;      // 0..511
            int kr  = idx >> 4;          // 0..31
            int c4  = idx & 15;          // 0..15
            float4 wv = *(const float4*)(W + (size_t)(kt * 32 + kr) * F_HID + c4 * 4);
            float4 tw = make_float4(f2tf32(wv.x), f2tf32(wv.y), f2tf32(wv.z), f2tf32(wv.w));
            *(float4*)&sW[kr][c4 * 4] = tw;
        }
        __syncthreads();

#pragma unroll
        for (int kc = 0; kc < 4; ++kc) {         // 32 / 8
            uint32_t b0[4], b1[4];
#pragma unroll
            for (int j = 0; j < 4; ++j) {
                int n = wn * 32 + j * 8 + gid;
                b0[j] = __float_as_uint(sW[kc * 8 + tig    ][n]);
                b1[j] = __float_as_uint(sW[kc * 8 + tig + 4][n]);
            }
            uint32_t a[2][4];
#pragma unroll
            for (int i = 0; i < 2; ++i) {
                int r = wm * 32 + i * 16;
                int k = kc * 8;
                a[i][0] = __float_as_uint(sX[r + gid    ][k + tig    ]);
                a[i][1] = __float_as_uint(sX[r + gid + 8][k + tig    ]);
                a[i][2] = __float_as_uint(sX[r + gid    ][k + tig + 4]);
                a[i][3] = __float_as_uint(sX[r + gid + 8][k + tig + 4]);
            }
#pragma unroll
            for (int i = 0; i < 2; ++i)
#pragma unroll
                for (int j = 0; j < 4; ++j) {
                    asm volatile(
                        "mma.sync.aligned.m16n8k8.row.col.f32.tf32.tf32.f32 "
                        "{%0,%1,%2,%3}, {%4,%5,%6,%7}, {%8,%9}, {%0,%1,%2,%3};"
                        : "+f"(c[i][j][0]), "+f"(c[i][j][1]),
                          "+f"(c[i][j][2]), "+f"(c[i][j][3])
                        : "r"(a[i][0]), "r"(a[i][1]), "r"(a[i][2]), "r"(a[i][3]),
                          "r"(b0[j]), "r"(b1[j]));
                }
        }
        __syncthreads();
    }

    // epilogue: c[i][j][0..1] -> row gr0, cols col..col+1 ; c[i][j][2..3] -> row gr0+8
#pragma unroll
    for (int i = 0; i < 2; ++i) {
        int gr0 = row0 + wm * 32 + i * 16 + gid;
        int gr1 = gr0 + 8;
        float ds0 = (gr0 < M) ? g_dis[gr0] : 0.f;
        float ds1 = (gr1 < M) ? g_dis[gr1] : 0.f;
#pragma unroll
        for (int j = 0; j < 4; ++j) {
            int col = wn * 32 + j * 8 + 2 * tig;
            if (gr0 < M) {
                float2 o = make_float2(c[i][j][0] * ds0, c[i][j][1] * ds0);
                *(float2*)(g_xws + (size_t)gr0 * F_HID + col) = o;
            }
            if (gr1 < M) {
                float2 o = make_float2(c[i][j][2] * ds1, c[i][j][3] * ds1);
                *(float2*)(g_xws + (size_t)gr1 * F_HID + col) = o;
            }
        }
    }
}

// ---------------------------------------------------------------------------
// gather layer 1: one warp per dst node, float2 per lane (64 feats)
//   h[d] = dis[d] * ( xws[d] + sum_s xws[s] )
// ---------------------------------------------------------------------------
__global__ void k_gather1(int N) {
    int warp = (blockIdx.x * blockDim.x + threadIdx.x) >> 5;
    int lane = threadIdx.x & 31;
    if (warp >= N) return;
    const int d = warp;
    int deg = g_cnt[d]; if (deg > CAP) deg = CAP;
    const int* bk = g_bucket + (size_t)d * CAP;

    // self term as accumulator seed (already pre-scaled by dis[d])
    float2 acc = *((const float2*)(g_xws + (size_t)d * F_HID) + lane);
    for (int i = 0; i < deg; ++i) {
        int s = bk[i];                                   // warp-broadcast
        float2 v = *((const float2*)(g_xws + (size_t)s * F_HID) + lane);
        acc.x += v.x;
        acc.y += v.y;
    }
    float dd = g_dis[d];
    float2 h = make_float2(dd * acc.x, dd * acc.y);
    *(float2*)(g_h + (size_t)d * F_HID + lane * 2) = h;
}

// ---------------------------------------------------------------------------
// GEMM2 with fused relu+bias on input and dis pre-scale on output:
//   g_hw2s[M,16] = ( relu(g_h + b1) @ W2[64,16] ) * dis
// ---------------------------------------------------------------------------
__global__ void k_gemm2(const float* __restrict__ W2, const float* __restrict__ b1,
                        int M) {
    __shared__ float sW[F_HID * F_OUT];   // 1024
    __shared__ float sH[16][65];
    int t = threadIdx.x;                  // 256 threads, 16 nodes/block
    for (int i = t; i < F_HID * F_OUT; i += 256) sW[i] = W2[i];
    int node0 = blockIdx.x * 16;
    for (int i = t; i < 1024; i += 256) {
        int r = i >> 6, c = i & 63;
        int gn = node0 + r;
        float hv = (gn < M) ? g_h[(size_t)gn * F_HID + c] : 0.f;
        sH[r][c] = fmaxf(hv + b1[c], 0.f);     // fused relu+bias
    }
    __syncthreads();
    int f = t & 15, nl = t >> 4;
    float acc = 0.f;
#pragma unroll
    for (int k = 0; k < F_HID; ++k) acc += sH[nl][k] * sW[k * F_OUT + f];
    int gn = node0 + nl;
    if (gn < M) g_hw2s[(size_t)gn * F_OUT + f] = acc * g_dis[gn];
}

// ---------------------------------------------------------------------------
// gather layer 2: 16 lanes per dst node (one float each)
//   out[d] = dis[d] * ( hw2s[d] + sum_s hw2s[s] ) + b2
// ---------------------------------------------------------------------------
__global__ void k_gather2(const float* __restrict__ b2, float* __restrict__ out,
                          int N) {
    int tid = blockIdx.x * blockDim.x + threadIdx.x;
    int node = tid >> 4;
    if (node >= N) return;
    int q = tid & 15;
    int deg = g_cnt[node]; if (deg > CAP) deg = CAP;
    const int* bk = g_bucket + (size_t)node * CAP;

    float acc = g_hw2s[(size_t)node * F_OUT + q];   // self term (pre-scaled)
    for (int i = 0; i < deg; ++i) {
        int s = bk[i];
        acc += g_hw2s[(size_t)s * F_OUT + q];
    }
    out[(size_t)node * F_OUT + q] = g_dis[node] * acc + b2[q];
}

// ---------------------------------------------------------------------------
extern "C" void kernel_launch(void* const* d_in, const int* in_sizes, int n_in,
                              void* d_out, int out_size) {
    // Bind inputs by element count (robust to metadata ordering); positional fallback.
    const float* x  = (const float*)d_in[0];
    const void*  ei = d_in[1];
    const float* W1 = (const float*)d_in[2];
    const float* b1 = (const float*)d_in[3];
    const float* W2 = (const float*)d_in[4];
    const float* b2 = (const float*)d_in[5];
    int x_elems = in_sizes[0];
    int e_elems = in_sizes[1];
    for (int i = 0; i < n_in; ++i) {
        int sz = in_sizes[i];
        if (sz == N_NODES * F_IN)      { x  = (const float*)d_in[i]; x_elems = sz; }
        else if (sz == 2 * E_MAX)      { ei = d_in[i];               e_elems = sz; }
        else if (sz == F_IN * F_HID)   { W1 = (const float*)d_in[i]; }
        else if (sz == F_HID)          { b1 = (const float*)d_in[i]; }
        else if (sz == F_HID * F_OUT)  { W2 = (const float*)d_in[i]; }
        else if (sz == F_OUT)          { b2 = (const float*)d_in[i]; }
    }
    float* out = (float*)d_out;

    const int N = x_elems / F_IN;       // 100000
    const int E = e_elems / 2;          // 1600000

    const int T = 256;

    // graph build chain, single stream
    k_prep<<<(N + T - 1) / T, T>>>((const int*)ei, N);
    k_build<<<(E + T - 1) / T, T>>>(ei, E);
    k_rsqrt_deg<<<(N + T - 1) / T, T>>>(N);

    // layer 1 (tf32 tensor-core GEMM, dis pre-scaled epilogue)
    k_gemm1<<<(N + 127) / 128, 256>>>(x, W1, N);
    k_gather1<<<(N * 32 + T - 1) / T, T>>>(N);

    // layer 2
    k_gemm2<<<(N + 15) / 16, 256>>>(W2, b1, N);
    k_gather2<<<(N * 16 + T - 1) / T, T>>>(b2, out, N);
}

// round 11
// speedup vs baseline: 1.3604x; 1.0274x over previous
#include <cuda_runtime.h>
#include <cuda_fp16.h>
#include <cstdint>

#define N_NODES 100000
#define F_IN    128
#define F_HID   64
#define F_OUT   16
#define E_MAX   1600000
#define CAP     128          // padded in-neighbor bucket capacity (Poisson(16) tail ~0)

// Scratch (allocation-free rule: __device__ globals).
// NOTE: never pass these as kernel args from host — host sees the shadow
// symbol and ATS on GB300 makes the bogus access succeed silently.
__device__ float   g_dis [N_NODES];             // rsqrt(1 + in-degree)
__device__ int     g_cnt [N_NODES];             // in-degree counters (zeroed per launch)
__device__ int     g_bucket[(size_t)N_NODES * CAP];  // in-neighbor src lists
__device__ __half2 g_xwsh[N_NODES * (F_HID / 2)];    // (x@W1)*dis, fp16 (gather payload)
__device__ float   g_h   [N_NODES * F_HID];          // layer-1 aggregated output (fp32)
__device__ __half  g_hw2sh[N_NODES * F_OUT];         // (relu(h+b1)@W2)*dis, fp16
__device__ int     g_is64;

__device__ __forceinline__ float f2tf32(float f) {
    uint32_t r;
    asm("cvt.rna.tf32.f32 %0, %1;" : "=r"(r) : "f"(f));
    return __uint_as_float(r);
}

// ---------------------------------------------------------------------------
// prep: zero counters; thread 0 also sniffs edge dtype
// (int64 little-endian with values < 2^31 has zero odd 32-bit words)
// ---------------------------------------------------------------------------
__global__ void k_prep(const int* __restrict__ ei32, int n) {
    int i = blockIdx.x * blockDim.x + threadIdx.x;
    if (i < n) g_cnt[i] = 0;
    if (i == 0) {
        int all_zero = 1;
#pragma unroll
        for (int j = 0; j < 16; ++j)
            if (ei32[2 * j + 1] != 0) all_zero = 0;
        g_is64 = all_zero;
    }
}

// ---------------------------------------------------------------------------
// bucket build: decode edge, cnt[dst]++ (also serves as degree), store src
// ---------------------------------------------------------------------------
__global__ void k_build(const void* __restrict__ ei, int E) {
    int e = blockIdx.x * blockDim.x + threadIdx.x;
    if (e >= E) return;
    int s, d;
    if (g_is64) {
        s = (int)((const long long*)ei)[e];
        d = (int)((const long long*)ei)[e + E];
    } else {
        s = ((const int*)ei)[e];
        d = ((const int*)ei)[e + E];
    }
    if (s < 0) s = 0; if (s >= N_NODES) s = N_NODES - 1;
    if (d < 0) d = 0; if (d >= N_NODES) d = N_NODES - 1;
    int pos = atomicAdd(&g_cnt[d], 1);
    if (pos < CAP) g_bucket[(size_t)d * CAP + pos] = s;
}

__global__ void k_rsqrt_deg(int n) {
    int i = blockIdx.x * blockDim.x + threadIdx.x;
    if (i < n) g_dis[i] = rsqrtf(1.0f + (float)g_cnt[i]);   // +1 = self-loop
}

// ---------------------------------------------------------------------------
// GEMM1 via tf32 mma.sync + fused dis pre-scale, fp16 output:
//   g_xwsh[M,64] = half( (X[M,128] @ W[128,64]) * dis )
// Block tile 128x64, 8 warps (4 M x 2 N), warp tile 32x32, mma m16n8k8.
// ---------------------------------------------------------------------------
__global__ void k_gemm1(const float* __restrict__ X, const float* __restrict__ W,
                        int M) {
    __shared__ float sX[128][36];   // [row][k], pad 4 -> fragment LDS conflict-free
    __shared__ float sW[32][72];    // [k][n],  pad 8 -> fragment LDS conflict-free

    const int t    = threadIdx.x;        // 256 threads
    const int lane = t & 31;
    const int warp = t >> 5;             // 0..7
    const int wm   = warp & 3;           // M group (32 rows)
    const int wn   = warp >> 2;          // N group (32 cols)
    const int gid  = lane >> 2;          // 0..7
    const int tig  = lane & 3;           // 0..3
    const int row0 = blockIdx.x * 128;

    float c[2][4][4];
#pragma unroll
    for (int i = 0; i < 2; i++)
#pragma unroll
        for (int j = 0; j < 4; j++)
#pragma unroll
            for (int k = 0; k < 4; k++) c[i][j][k] = 0.f;

    for (int kt = 0; kt < 4; ++kt) {     // K = 128 / 32
        // load X tile: 128 rows x 32 k  (1024 float4, 4 per thread)
#pragma unroll
        for (int it = 0; it < 4; ++it) {
            int idx = t + it * 256;      // 0..1023
            int row = idx >> 3;          // 0..127
            int c4  = idx & 7;           // 0..7
            int gr  = row0 + row;
            float4 v = make_float4(0.f, 0.f, 0.f, 0.f);
            if (gr < M)
                v = *(const float4*)(X + (size_t)gr * F_IN + kt * 32 + c4 * 4);
            float4 tv = make_float4(f2tf32(v.x), f2tf32(v.y), f2tf32(v.z), f2tf32(v.w));
            *(float4*)&sX[row][c4 * 4] = tv;
        }
        // load W tile: 32 k x 64 n (512 float4, 2 per thread)
#pragma unroll
        for (int it = 0; it < 2; ++it) {
            int idx = t + it * 256;      // 0..511
            int kr  = idx >> 4;          // 0..31
            int c4  = idx & 15;          // 0..15
            float4 wv = *(const float4*)(W + (size_t)(kt * 32 + kr) * F_HID + c4 * 4);
            float4 tw = make_float4(f2tf32(wv.x), f2tf32(wv.y), f2tf32(wv.z), f2tf32(wv.w));
            *(float4*)&sW[kr][c4 * 4] = tw;
        }
        __syncthreads();

#pragma unroll
        for (int kc = 0; kc < 4; ++kc) {         // 32 / 8
            uint32_t b0[4], b1[4];
#pragma unroll
            for (int j = 0; j < 4; ++j) {
                int n = wn * 32 + j * 8 + gid;
                b0[j] = __float_as_uint(sW[kc * 8 + tig    ][n]);
                b1[j] = __float_as_uint(sW[kc * 8 + tig + 4][n]);
            }
            uint32_t a[2][4];
#pragma unroll
            for (int i = 0; i < 2; ++i) {
                int r = wm * 32 + i * 16;
                int k = kc * 8;
                a[i][0] = __float_as_uint(sX[r + gid    ][k + tig    ]);
                a[i][1] = __float_as_uint(sX[r + gid + 8][k + tig    ]);
                a[i][2] = __float_as_uint(sX[r + gid    ][k + tig + 4]);
                a[i][3] = __float_as_uint(sX[r + gid + 8][k + tig + 4]);
            }
#pragma unroll
            for (int i = 0; i < 2; ++i)
#pragma unroll
                for (int j = 0; j < 4; ++j) {
                    asm volatile(
                        "mma.sync.aligned.m16n8k8.row.col.f32.tf32.tf32.f32 "
                        "{%0,%1,%2,%3}, {%4,%5,%6,%7}, {%8,%9}, {%0,%1,%2,%3};"
                        : "+f"(c[i][j][0]), "+f"(c[i][j][1]),
                          "+f"(c[i][j][2]), "+f"(c[i][j][3])
                        : "r"(a[i][0]), "r"(a[i][1]), "r"(a[i][2]), "r"(a[i][3]),
                          "r"(b0[j]), "r"(b1[j]));
                }
        }
        __syncthreads();
    }

    // epilogue: c[i][j][0..1] -> row gr0, cols col..col+1 (one half2);
    //           c[i][j][2..3] -> row gr0+8
#pragma unroll
    for (int i = 0; i < 2; ++i) {
        int gr0 = row0 + wm * 32 + i * 16 + gid;
        int gr1 = gr0 + 8;
        float ds0 = (gr0 < M) ? g_dis[gr0] : 0.f;
        float ds1 = (gr1 < M) ? g_dis[gr1] : 0.f;
#pragma unroll
        for (int j = 0; j < 4; ++j) {
            int col = wn * 32 + j * 8 + 2 * tig;     // even
            if (gr0 < M)
                g_xwsh[(size_t)gr0 * (F_HID / 2) + col / 2] =
                    __floats2half2_rn(c[i][j][0] * ds0, c[i][j][1] * ds0);
            if (gr1 < M)
                g_xwsh[(size_t)gr1 * (F_HID / 2) + col / 2] =
                    __floats2half2_rn(c[i][j][2] * ds1, c[i][j][3] * ds1);
        }
    }
}

// ---------------------------------------------------------------------------
// gather layer 1: one warp per dst node, one half2 (2 feats) per lane
//   h[d] = dis[d] * ( xws[d] + sum_s xws[s] )       (fp32 accumulate)
// Row payload is 128B -> one full sector per row, fully coalesced.
// ---------------------------------------------------------------------------
__global__ void k_gather1(int N) {
    int warp = (blockIdx.x * blockDim.x + threadIdx.x) >> 5;
    int lane = threadIdx.x & 31;
    if (warp >= N) return;
    const int d = warp;
    int deg = g_cnt[d]; if (deg > CAP) deg = CAP;
    const int* bk = g_bucket + (size_t)d * CAP;

    // self term as accumulator seed (already pre-scaled by dis[d])
    float2 acc = __half22float2(g_xwsh[(size_t)d * (F_HID / 2) + lane]);
    for (int i = 0; i < deg; ++i) {
        int s = bk[i];                                   // warp-broadcast
        float2 v = __half22float2(g_xwsh[(size_t)s * (F_HID / 2) + lane]);
        acc.x += v.x;
        acc.y += v.y;
    }
    float dd = g_dis[d];
    float2 h = make_float2(dd * acc.x, dd * acc.y);
    *(float2*)(g_h + (size_t)d * F_HID + lane * 2) = h;
}

// ---------------------------------------------------------------------------
// GEMM2 with fused relu+bias on input and dis pre-scale on output (fp16 out):
//   g_hw2sh[M,16] = half( ( relu(g_h + b1) @ W2[64,16] ) * dis )
// ---------------------------------------------------------------------------
__global__ void k_gemm2(const float* __restrict__ W2, const float* __restrict__ b1,
                        int M) {
    __shared__ float sW[F_HID * F_OUT];   // 1024
    __shared__ float sH[16][65];
    int t = threadIdx.x;                  // 256 threads, 16 nodes/block
    for (int i = t; i < F_HID * F_OUT; i += 256) sW[i] = W2[i];
    int node0 = blockIdx.x * 16;
    for (int i = t; i < 1024; i += 256) {
        int r = i >> 6, c = i & 63;
        int gn = node0 + r;
        float hv = (gn < M) ? g_h[(size_t)gn * F_HID + c] : 0.f;
        sH[r][c] = fmaxf(hv + b1[c], 0.f);     // fused relu+bias
    }
    __syncthreads();
    int f = t & 15, nl = t >> 4;
    float acc = 0.f;
#pragma unroll
    for (int k = 0; k < F_HID; ++k) acc += sH[nl][k] * sW[k * F_OUT + f];
    int gn = node0 + nl;
    if (gn < M) g_hw2sh[(size_t)gn * F_OUT + f] = __float2half(acc * g_dis[gn]);
}

// ---------------------------------------------------------------------------
// gather layer 2: 16 lanes per dst node (one half each, fp32 accumulate)
//   out[d] = dis[d] * ( hw2s[d] + sum_s hw2s[s] ) + b2
// ---------------------------------------------------------------------------
__global__ void k_gather2(const float* __restrict__ b2, float* __restrict__ out,
                          int N) {
    int tid = blockIdx.x * blockDim.x + threadIdx.x;
    int node = tid >> 4;
    if (node >= N) return;
    int q = tid & 15;
    int deg = g_cnt[node]; if (deg > CAP) deg = CAP;
    const int* bk = g_bucket + (size_t)node * CAP;

    float acc = __half2float(g_hw2sh[(size_t)node * F_OUT + q]);   // self term
    for (int i = 0; i < deg; ++i) {
        int s = bk[i];
        acc += __half2float(g_hw2sh[(size_t)s * F_OUT + q]);
    }
    out[(size_t)node * F_OUT + q] = g_dis[node] * acc + b2[q];
}

// ---------------------------------------------------------------------------
extern "C" void kernel_launch(void* const* d_in, const int* in_sizes, int n_in,
                              void* d_out, int out_size) {
    // Bind inputs by element count (robust to metadata ordering); positional fallback.
    const float* x  = (const float*)d_in[0];
    const void*  ei = d_in[1];
    const float* W1 = (const float*)d_in[2];
    const float* b1 = (const float*)d_in[3];
    const float* W2 = (const float*)d_in[4];
    const float* b2 = (const float*)d_in[5];
    int x_elems = in_sizes[0];
    int e_elems = in_sizes[1];
    for (int i = 0; i < n_in; ++i) {
        int sz = in_sizes[i];
        if (sz == N_NODES * F_IN)      { x  = (const float*)d_in[i]; x_elems = sz; }
        else if (sz == 2 * E_MAX)      { ei = d_in[i];               e_elems = sz; }
        else if (sz == F_IN * F_HID)   { W1 = (const float*)d_in[i]; }
        else if (sz == F_HID)          { b1 = (const float*)d_in[i]; }
        else if (sz == F_HID * F_OUT)  { W2 = (const float*)d_in[i]; }
        else if (sz == F_OUT)          { b2 = (const float*)d_in[i]; }
    }
    float* out = (float*)d_out;

    const int N = x_elems / F_IN;       // 100000
    const int E = e_elems / 2;          // 1600000

    const int T = 256;

    // graph build chain, single stream
    k_prep<<<(N + T - 1) / T, T>>>((const int*)ei, N);
    k_build<<<(E + T - 1) / T, T>>>(ei, E);
    k_rsqrt_deg<<<(N + T - 1) / T, T>>>(N);

    // layer 1 (tf32 tensor-core GEMM, dis pre-scaled fp16 epilogue)
    k_gemm1<<<(N + 127) / 128, 256>>>(x, W1, N);
    k_gather1<<<(N * 32 + T - 1) / T, T>>>(N);

    // layer 2
    k_gemm2<<<(N + 15) / 16, 256>>>(W2, b1, N);
    k_gather2<<<(N * 16 + T - 1) / T, T>>>(b2, out, N);
}

// round 12
// speedup vs baseline: 1.3847x; 1.0179x over previous
#include <cuda_runtime.h>
#include <cuda_fp16.h>
#include <cstdint>

#define N_NODES 100000
#define F_IN    128
#define F_HID   64
#define F_OUT   16
#define E_MAX   1600000
#define CAP     128          // padded in-neighbor bucket capacity (Poisson(16) tail ~0)

// Scratch (allocation-free rule: __device__ globals).
// NOTE: never pass these as kernel args from host — host sees the shadow
// symbol and ATS on GB300 makes the bogus access succeed silently.
__device__ float   g_dis [N_NODES];             // rsqrt(1 + in-degree)
__device__ int     g_cnt [N_NODES];             // in-degree counters (zeroed per launch)
__device__ int     g_bucket[(size_t)N_NODES * CAP];  // in-neighbor src lists
__device__ __half2 g_xwsh[N_NODES * (F_HID / 2)];    // (x@W1)*dis, fp16 (gather payload)
__device__ __half  g_hw2sh[N_NODES * F_OUT];         // (relu(h+b1)@W2)*dis, fp16
__device__ int     g_is64;

__device__ __forceinline__ uint32_t f2tf32u(float f) {
    uint32_t r;
    asm("cvt.rna.tf32.f32 %0, %1;" : "=r"(r) : "f"(f));
    return r;
}

__device__ __forceinline__ uint32_t smem_u32(const void* p) {
    return (uint32_t)__cvta_generic_to_shared(p);
}

__device__ __forceinline__ void cp_async16(uint32_t dst, const void* src, bool valid) {
    int sz = valid ? 16 : 0;   // src-size 0 -> zero-fill
    asm volatile("cp.async.ca.shared.global [%0], [%1], 16, %2;"
                 :: "r"(dst), "l"(src), "r"(sz) : "memory");
}

// ---------------------------------------------------------------------------
// prep: zero counters; thread 0 also sniffs edge dtype
// (int64 little-endian with values < 2^31 has zero odd 32-bit words)
// ---------------------------------------------------------------------------
__global__ void k_prep(const int* __restrict__ ei32, int n) {
    int i = blockIdx.x * blockDim.x + threadIdx.x;
    if (i < n) g_cnt[i] = 0;
    if (i == 0) {
        int all_zero = 1;
#pragma unroll
        for (int j = 0; j < 16; ++j)
            if (ei32[2 * j + 1] != 0) all_zero = 0;
        g_is64 = all_zero;
    }
}

// ---------------------------------------------------------------------------
// bucket build: decode edge, cnt[dst]++ (also serves as degree), store src
// ---------------------------------------------------------------------------
__global__ void k_build(const void* __restrict__ ei, int E) {
    int e = blockIdx.x * blockDim.x + threadIdx.x;
    if (e >= E) return;
    int s, d;
    if (g_is64) {
        s = (int)((const long long*)ei)[e];
        d = (int)((const long long*)ei)[e + E];
    } else {
        s = ((const int*)ei)[e];
        d = ((const int*)ei)[e + E];
    }
    if (s < 0) s = 0; if (s >= N_NODES) s = N_NODES - 1;
    if (d < 0) d = 0; if (d >= N_NODES) d = N_NODES - 1;
    int pos = atomicAdd(&g_cnt[d], 1);
    if (pos < CAP) g_bucket[(size_t)d * CAP + pos] = s;
}

__global__ void k_rsqrt_deg(int n) {
    int i = blockIdx.x * blockDim.x + threadIdx.x;
    if (i < n) g_dis[i] = rsqrtf(1.0f + (float)g_cnt[i]);   // +1 = self-loop
}

// ---------------------------------------------------------------------------
// GEMM1 via tf32 mma.sync, cp.async double-buffered K pipeline,
// fused dis pre-scale, fp16 output:
//   g_xwsh[M,64] = half( (X[M,128] @ W[128,64]) * dis )
// Block 128x64, 8 warps (4 M x 2 N), warp tile 32x32, mma m16n8k8,
// K in 8 chunks of 16, 2 smem stages.
// ---------------------------------------------------------------------------
__global__ void k_gemm1(const float* __restrict__ X, const float* __restrict__ W,
                        int M) {
    __shared__ float sX[2][128][20];   // [stage][row][k], pad 4 (frag LDS conflict-free)
    __shared__ float sW[2][16][72];    // [stage][k][n],  pad 8 (frag LDS conflict-free)

    const int t    = threadIdx.x;        // 256 threads
    const int lane = t & 31;
    const int warp = t >> 5;             // 0..7
    const int wm   = warp & 3;           // M group (32 rows)
    const int wn   = warp >> 2;          // N group (32 cols)
    const int gid  = lane >> 2;          // 0..7
    const int tig  = lane & 3;           // 0..3
    const int row0 = blockIdx.x * 128;

    // per-thread cp.async coordinates
    const int xr0 = t >> 2;              // row for idx=t        (0..63)
    const int xc0 = (t & 3) * 4;         // k-col for idx=t
    const int xr1 = (t + 256) >> 2;      // row for idx=t+256    (64..127)
    const int wkr = t >> 4;              // W k-row  (0..15)
    const int wc  = (t & 15) * 4;        // W n-col

    auto issue_chunk = [&](int kt, int st) {
        const float* xs0 = X + (size_t)(row0 + xr0) * F_IN + kt * 16 + xc0;
        const float* xs1 = X + (size_t)(row0 + xr1) * F_IN + kt * 16 + xc0;
        cp_async16(smem_u32(&sX[st][xr0][xc0]), xs0, row0 + xr0 < M);
        cp_async16(smem_u32(&sX[st][xr1][xc0]), xs1, row0 + xr1 < M);
        const float* ws = W + (size_t)(kt * 16 + wkr) * F_HID + wc;
        cp_async16(smem_u32(&sW[st][wkr][wc]), ws, true);
        asm volatile("cp.async.commit_group;" ::: "memory");
    };

    float c[2][4][4];
#pragma unroll
    for (int i = 0; i < 2; i++)
#pragma unroll
        for (int j = 0; j < 4; j++)
#pragma unroll
            for (int k = 0; k < 4; k++) c[i][j][k] = 0.f;

    issue_chunk(0, 0);

    int st = 0;
    for (int kt = 0; kt < 8; ++kt) {     // K = 128 / 16
        if (kt < 7) {
            issue_chunk(kt + 1, st ^ 1);
            asm volatile("cp.async.wait_group 1;" ::: "memory");
        } else {
            asm volatile("cp.async.wait_group 0;" ::: "memory");
        }
        __syncthreads();

#pragma unroll
        for (int kc = 0; kc < 2; ++kc) {         // 16 / 8
            uint32_t b0[4], b1[4];
#pragma unroll
            for (int j = 0; j < 4; ++j) {
                int n = wn * 32 + j * 8 + gid;
                b0[j] = f2tf32u(sW[st][kc * 8 + tig    ][n]);
                b1[j] = f2tf32u(sW[st][kc * 8 + tig + 4][n]);
            }
            uint32_t a[2][4];
#pragma unroll
            for (int i = 0; i < 2; ++i) {
                int r = wm * 32 + i * 16;
                int k = kc * 8;
                a[i][0] = f2tf32u(sX[st][r + gid    ][k + tig    ]);
                a[i][1] = f2tf32u(sX[st][r + gid + 8][k + tig    ]);
                a[i][2] = f2tf32u(sX[st][r + gid    ][k + tig + 4]);
                a[i][3] = f2tf32u(sX[st][r + gid + 8][k + tig + 4]);
            }
#pragma unroll
            for (int i = 0; i < 2; ++i)
#pragma unroll
                for (int j = 0; j < 4; ++j) {
                    asm volatile(
                        "mma.sync.aligned.m16n8k8.row.col.f32.tf32.tf32.f32 "
                        "{%0,%1,%2,%3}, {%4,%5,%6,%7}, {%8,%9}, {%0,%1,%2,%3};"
                        : "+f"(c[i][j][0]), "+f"(c[i][j][1]),
                          "+f"(c[i][j][2]), "+f"(c[i][j][3])
                        : "r"(a[i][0]), "r"(a[i][1]), "r"(a[i][2]), "r"(a[i][3]),
                          "r"(b0[j]), "r"(b1[j]));
                }
        }
        __syncthreads();
        st ^= 1;
    }

    // epilogue: c[i][j][0..1] -> row gr0 (half2), c[i][j][2..3] -> row gr0+8
#pragma unroll
    for (int i = 0; i < 2; ++i) {
        int gr0 = row0 + wm * 32 + i * 16 + gid;
        int gr1 = gr0 + 8;
        float ds0 = (gr0 < M) ? g_dis[gr0] : 0.f;
        float ds1 = (gr1 < M) ? g_dis[gr1] : 0.f;
#pragma unroll
        for (int j = 0; j < 4; ++j) {
            int col = wn * 32 + j * 8 + 2 * tig;     // even
            if (gr0 < M)
                g_xwsh[(size_t)gr0 * (F_HID / 2) + col / 2] =
                    __floats2half2_rn(c[i][j][0] * ds0, c[i][j][1] * ds0);
            if (gr1 < M)
                g_xwsh[(size_t)gr1 * (F_HID / 2) + col / 2] =
                    __floats2half2_rn(c[i][j][2] * ds1, c[i][j][3] * ds1);
        }
    }
}

// ---------------------------------------------------------------------------
// FUSED gather1 + relu/bias + GEMM2 + dis pre-scale:
// one warp per dst node d:
//   h(2 feats/lane) = dis[d] * ( xws[d] + sum_s xws[s] )        (fp32 acc)
//   hr = relu(h + b1)
//   p[f] = sum_c hr[c] * W2[c][f]   via per-lane partials + warp butterfly
//   g_hw2sh[d][f] = half( p[f] * dis[d] )
// Eliminates the g_h round-trip (51 MB of traffic) and one launch.
// ---------------------------------------------------------------------------
__global__ void k_gather1g2(const float* __restrict__ W2,
                            const float* __restrict__ b1, int N) {
    __shared__ float sW2[F_HID][17];     // pad 17 -> 2-way max on row-pair reads
    int t = threadIdx.x;                 // 256 threads = 8 nodes/block
    for (int i = t; i < F_HID * F_OUT; i += 256)
        sW2[i >> 4][i & 15] = W2[i];
    __syncthreads();

    int warpid = (blockIdx.x * blockDim.x + t) >> 5;
    int lane = t & 31;
    if (warpid >= N) return;
    const int d = warpid;
    int deg = g_cnt[d]; if (deg > CAP) deg = CAP;
    const int* bk = g_bucket + (size_t)d * CAP;

    // aggregate (self term as seed; rows pre-scaled by dis[src])
    float2 acc = __half22float2(g_xwsh[(size_t)d * (F_HID / 2) + lane]);
    for (int i = 0; i < deg; ++i) {
        int s = bk[i];                                   // warp-broadcast
        float2 v = __half22float2(g_xwsh[(size_t)s * (F_HID / 2) + lane]);
        acc.x += v.x;
        acc.y += v.y;
    }
    float dd = g_dis[d];
    float2 bb = *(const float2*)(b1 + 2 * lane);
    float h0 = fmaxf(dd * acc.x + bb.x, 0.f);
    float h1 = fmaxf(dd * acc.y + bb.y, 0.f);

    // per-lane partial of the 64x16 GEMV (lane owns feats 2*lane, 2*lane+1)
    float p[F_OUT];
#pragma unroll
    for (int f = 0; f < F_OUT; ++f)
        p[f] = h0 * sW2[2 * lane][f] + h1 * sW2[2 * lane + 1][f];

    // butterfly reduce all 16 partials across the warp
#pragma unroll
    for (int m = 16; m >= 1; m >>= 1)
#pragma unroll
        for (int f = 0; f < F_OUT; ++f)
            p[f] += __shfl_xor_sync(0xFFFFFFFFu, p[f], m);

    if (lane < F_OUT)
        g_hw2sh[(size_t)d * F_OUT + lane] = __float2half(p[lane] * dd);
}

// ---------------------------------------------------------------------------
// gather layer 2: 16 lanes per dst node (one half each, fp32 accumulate)
//   out[d] = dis[d] * ( hw2s[d] + sum_s hw2s[s] ) + b2
// ---------------------------------------------------------------------------
__global__ void k_gather2(const float* __restrict__ b2, float* __restrict__ out,
                          int N) {
    int tid = blockIdx.x * blockDim.x + threadIdx.x;
    int node = tid >> 4;
    if (node >= N) return;
    int q = tid & 15;
    int deg = g_cnt[node]; if (deg > CAP) deg = CAP;
    const int* bk = g_bucket + (size_t)node * CAP;

    float acc = __half2float(g_hw2sh[(size_t)node * F_OUT + q]);   // self term
    for (int i = 0; i < deg; ++i) {
        int s = bk[i];
        acc += __half2float(g_hw2sh[(size_t)s * F_OUT + q]);
    }
    out[(size_t)node * F_OUT + q] = g_dis[node] * acc + b2[q];
}

// ---------------------------------------------------------------------------
extern "C" void kernel_launch(void* const* d_in, const int* in_sizes, int n_in,
                              void* d_out, int out_size) {
    // Bind inputs by element count (robust to metadata ordering); positional fallback.
    const float* x  = (const float*)d_in[0];
    const void*  ei = d_in[1];
    const float* W1 = (const float*)d_in[2];
    const float* b1 = (const float*)d_in[3];
    const float* W2 = (const float*)d_in[4];
    const float* b2 = (const float*)d_in[5];
    int x_elems = in_sizes[0];
    int e_elems = in_sizes[1];
    for (int i = 0; i < n_in; ++i) {
        int sz = in_sizes[i];
        if (sz == N_NODES * F_IN)      { x  = (const float*)d_in[i]; x_elems = sz; }
        else if (sz == 2 * E_MAX)      { ei = d_in[i];               e_elems = sz; }
        else if (sz == F_IN * F_HID)   { W1 = (const float*)d_in[i]; }
        else if (sz == F_HID)          { b1 = (const float*)d_in[i]; }
        else if (sz == F_HID * F_OUT)  { W2 = (const float*)d_in[i]; }
        else if (sz == F_OUT)          { b2 = (const float*)d_in[i]; }
    }
    float* out = (float*)d_out;

    const int N = x_elems / F_IN;       // 100000
    const int E = e_elems / 2;          // 1600000

    const int T = 256;

    // graph build chain, single stream
    k_prep<<<(N + T - 1) / T, T>>>((const int*)ei, N);
    k_build<<<(E + T - 1) / T, T>>>(ei, E);
    k_rsqrt_deg<<<(N + T - 1) / T, T>>>(N);

    // layer 1 GEMM (tf32 mma + cp.async pipeline, fp16 pre-scaled epilogue)
    k_gemm1<<<(N + 127) / 128, 256>>>(x, W1, N);

    // fused layer-1 aggregation + layer-2 GEMM
    k_gather1g2<<<(N * 32 + T - 1) / T, T>>>(W2, b1, N);

    // layer-2 aggregation + bias
    k_gather2<<<(N * 16 + T - 1) / T, T>>>(b2, out, N);
}